// round 11
// baseline (speedup 1.0000x reference)
#include <cuda_runtime.h>
#include <cstdint>

constexpr int N_IN   = 16384;
constexpr int T_OUT  = 8195;           // ((N+13)-8)/2+1
constexpr int OUTROW = 2 * T_OUT;      // 16390

constexpr int THREADS        = 256;
constexpr int WARPS          = THREADS / 32;   // 8
constexpr int T_PER_WARP     = 128;            // 4 t per lane
constexpr int WARPS_PER_ROW  = 64;             // t 0..8191; t 8192..8194 via tail lanes
constexpr int BLOCKS_PER_ROW = WARPS_PER_ROW / WARPS;   // 8
constexpr int ROWS_PER_CTA   = 2;

// time-reversed filters (compile-time immediates -> FFMA-imm)
__device__ constexpr float LO[8] = {  0.23037781330885523f,  0.7148465705525415f,
                                      0.6308807679295904f,  -0.02798376941698385f,
                                     -0.18703481171888114f,  0.030841381835986965f,
                                      0.032883011666982945f,-0.010597401784997278f };
__device__ constexpr float HI[8] = { -0.010597401784997278f,-0.032883011666982945f,
                                      0.030841381835986965f, 0.18703481171888114f,
                                     -0.02798376941698385f, -0.6308807679295904f,
                                      0.7148465705525415f,  -0.23037781330885523f };

// sig[i] -> x index with symmetric mirror (verified rel_err==0)
__device__ __forceinline__ int map_sig(int i) {
    int m = i - 6;
    m = (m < 0) ? (-1 - m) : m;
    m = (m >= N_IN) ? (2 * N_IN - 1 - m) : m;
    return m;
}

// scalar mirrored path for boundary t's
__device__ __forceinline__ void slow_t(const float* __restrict__ xr, int t,
                                       float& a, float& d) {
    a = 0.f; d = 0.f;
    #pragma unroll
    for (int j = 0; j < 8; j++) {
        const float s = __ldg(xr + map_sig(2 * t + j));
        a = fmaf(LO[j], s, a);
        d = fmaf(HI[j], s, d);
    }
}

// 256-bit global load (sm_100+): 8 consecutive floats, 32B-aligned address
__device__ __forceinline__ void ldg256(const float* __restrict__ p, float r[8]) {
    asm ("ld.global.nc.v8.f32 {%0,%1,%2,%3,%4,%5,%6,%7}, [%8];"
         : "=f"(r[0]), "=f"(r[1]), "=f"(r[2]), "=f"(r[3]),
           "=f"(r[4]), "=f"(r[5]), "=f"(r[6]), "=f"(r[7])
         : "l"(p));
}

// compute one row-tile: window f[0..13] assembled from own regs + neighbor shfl
__device__ __forceinline__ void compute_tile(const float r[8], int lane,
                                             const float p[8],
                                             float& ca0, float& ca1, float& ca2, float& ca3,
                                             float& cd0, float& cd1, float& cd2, float& cd3)
{
    float n[8];
    #pragma unroll
    for (int j = 0; j < 8; j++)
        n[j] = __shfl_down_sync(0xffffffffu, r[j], 1);
    if (lane == 31) {
        #pragma unroll
        for (int j = 0; j < 8; j++) n[j] = p[j];
    }
    const float f[14] = { r[2], r[3], r[4], r[5], r[6], r[7],
                          n[0], n[1], n[2], n[3], n[4], n[5], n[6], n[7] };
    ca0=0.f; ca1=0.f; ca2=0.f; ca3=0.f;
    cd0=0.f; cd1=0.f; cd2=0.f; cd3=0.f;
    #pragma unroll
    for (int j = 0; j < 8; j++) {
        ca0 = fmaf(LO[j], f[j    ], ca0);  cd0 = fmaf(HI[j], f[j    ], cd0);
        ca1 = fmaf(LO[j], f[j + 2], ca1);  cd1 = fmaf(HI[j], f[j + 2], cd1);
        ca2 = fmaf(LO[j], f[j + 4], ca2);  cd2 = fmaf(HI[j], f[j + 4], cd2);
        ca3 = fmaf(LO[j], f[j + 6], ca3);  cd3 = fmaf(HI[j], f[j + 6], cd3);
    }
}

// PAR = (row * OUTROW + t) alignment class; compile-time per row slot
template<int PAR>
__device__ __forceinline__ void store_tile(float* __restrict__ orow, int t, int lane,
                                           float ca0, float ca1, float ca2, float ca3,
                                           float cd0, float cd1, float cd2, float cd3)
{
    float* __restrict__ gA = orow + t;
    float* __restrict__ gD = orow + T_OUT + t;
    if (PAR == 0) {
        // cA aligned directly; cD shift 1
        *reinterpret_cast<float4*>(gA) = make_float4(ca0, ca1, ca2, ca3);
        const float nd0 = __shfl_down_sync(0xffffffffu, cd0, 1);
        if (lane < 31) {
            *reinterpret_cast<float4*>(gD + 1) = make_float4(cd1, cd2, cd3, nd0);
        } else {
            gD[1] = cd1; gD[2] = cd2; gD[3] = cd3;
        }
        if (lane == 0) gD[0] = cd0;
    } else {
        // cA shift 2; cD shift 3
        const float na0 = __shfl_down_sync(0xffffffffu, ca0, 1);
        const float na1 = __shfl_down_sync(0xffffffffu, ca1, 1);
        if (lane < 31) {
            *reinterpret_cast<float4*>(gA + 2) = make_float4(ca2, ca3, na0, na1);
        } else {
            gA[2] = ca2; gA[3] = ca3;
        }
        if (lane == 0) { gA[0] = ca0; gA[1] = ca1; }
        const float nd0 = __shfl_down_sync(0xffffffffu, cd0, 1);
        const float nd1 = __shfl_down_sync(0xffffffffu, cd1, 1);
        const float nd2 = __shfl_down_sync(0xffffffffu, cd2, 1);
        if (lane < 31) {
            *reinterpret_cast<float4*>(gD + 3) = make_float4(cd3, nd0, nd1, nd2);
        } else {
            gD[3] = cd3;
        }
        if (lane == 0) { gD[0] = cd0; gD[1] = cd1; gD[2] = cd2; }
    }
}

__global__ __launch_bounds__(THREADS) void dwt_kernel(const float* __restrict__ x,
                                                      float* __restrict__ out)
{
    const int wid  = threadIdx.x >> 5;
    const int lane = threadIdx.x & 31;
    const int wir  = blockIdx.x * WARPS + wid;           // warp index within row, 0..63
    const int row0 = blockIdx.y * ROWS_PER_CTA;          // even
    const int row1 = row0 + 1;                           // odd

    const float* __restrict__ xr0 = x + (size_t)row0 * N_IN;
    const float* __restrict__ xr1 = x + (size_t)row1 * N_IN;
    float* __restrict__ orow0 = out + (size_t)row0 * OUTROW;
    float* __restrict__ orow1 = out + (size_t)row1 * OUTROW;

    const int t = wir * T_PER_WARP + 4 * lane;           // this lane's 4-t start
    const int b = 2 * t - 8;                             // data base (mult of 8)
    const bool edge = (wir == 0);                        // only warp 0 can underflow

    int b0 = b;
    if (edge) b0 = max(b, 0);                            // stays 32B-aligned

    // ---- front-batched independent loads (MLP 2; lane 31: 4) ----
    float r0[8], r1[8];
    ldg256(xr0 + b0, r0);
    ldg256(xr1 + b0, r1);

    float p0[8], p1[8];
    if (lane == 31) {
        int b1 = b + 8;
        if (edge) b1 = max(b1, 0);
        ldg256(xr0 + b1, p0);
        ldg256(xr1 + b1, p1);
    }

    const bool bdry = (t < 4) | (t + 3 > 8190);

    // ---- row0 (even parity) ----
    {
        float ca0, ca1, ca2, ca3, cd0, cd1, cd2, cd3;
        compute_tile(r0, lane, p0, ca0, ca1, ca2, ca3, cd0, cd1, cd2, cd3);
        if (bdry) {
            if (t     < 4 || t     > 8190) slow_t(xr0, t,     ca0, cd0);
            if (t + 1 < 4 || t + 1 > 8190) slow_t(xr0, t + 1, ca1, cd1);
            if (t + 2 < 4 || t + 2 > 8190) slow_t(xr0, t + 2, ca2, cd2);
            if (t + 3 < 4 || t + 3 > 8190) slow_t(xr0, t + 3, ca3, cd3);
        }
        store_tile<0>(orow0, t, lane, ca0, ca1, ca2, ca3, cd0, cd1, cd2, cd3);
    }

    // ---- row1 (odd parity) ----
    {
        float ca0, ca1, ca2, ca3, cd0, cd1, cd2, cd3;
        compute_tile(r1, lane, p1, ca0, ca1, ca2, ca3, cd0, cd1, cd2, cd3);
        if (bdry) {
            if (t     < 4 || t     > 8190) slow_t(xr1, t,     ca0, cd0);
            if (t + 1 < 4 || t + 1 > 8190) slow_t(xr1, t + 1, ca1, cd1);
            if (t + 2 < 4 || t + 2 > 8190) slow_t(xr1, t + 2, ca2, cd2);
            if (t + 3 < 4 || t + 3 > 8190) slow_t(xr1, t + 3, ca3, cd3);
        }
        store_tile<1>(orow1, t, lane, ca0, ca1, ca2, ca3, cd0, cd1, cd2, cd3);
    }

    // leftover t = 8192..8194 (all mirrored-boundary): 3 lanes of last warp, both rows
    if (wir == WARPS_PER_ROW - 1 && lane < 3) {
        const int tv = 8192 + lane;
        float a, d;
        slow_t(xr0, tv, a, d);
        orow0[tv]         = a;
        orow0[T_OUT + tv] = d;
        slow_t(xr1, tv, a, d);
        orow1[tv]         = a;
        orow1[T_OUT + tv] = d;
    }
}

extern "C" void kernel_launch(void* const* d_in, const int* in_sizes, int n_in,
                              void* d_out, int out_size)
{
    const float* x = (const float*)d_in[0];
    float* out = (float*)d_out;
    const int rows = in_sizes[0] / N_IN;   // 4096
    dim3 grid(BLOCKS_PER_ROW, rows / ROWS_PER_CTA);
    dwt_kernel<<<grid, THREADS>>>(x, out);
}

// round 12
// speedup vs baseline: 1.0035x; 1.0035x over previous
#include <cuda_runtime.h>
#include <cstdint>

constexpr int N_IN   = 16384;
constexpr int T_OUT  = 8195;           // ((N+13)-8)/2+1
constexpr int OUTROW = 2 * T_OUT;      // 16390

constexpr int THREADS        = 256;
constexpr int WARPS          = THREADS / 32;   // 8
constexpr int T_PER_WARP     = 128;            // 4 t per lane
constexpr int WARPS_PER_ROW  = 64;             // t 0..8191; t 8192..8194 via tail lanes
constexpr int BLOCKS_PER_ROW = WARPS_PER_ROW / WARPS;   // 8

// time-reversed filters (compile-time immediates -> FFMA-imm)
__device__ constexpr float LO[8] = {  0.23037781330885523f,  0.7148465705525415f,
                                      0.6308807679295904f,  -0.02798376941698385f,
                                     -0.18703481171888114f,  0.030841381835986965f,
                                      0.032883011666982945f,-0.010597401784997278f };
__device__ constexpr float HI[8] = { -0.010597401784997278f,-0.032883011666982945f,
                                      0.030841381835986965f, 0.18703481171888114f,
                                     -0.02798376941698385f, -0.6308807679295904f,
                                      0.7148465705525415f,  -0.23037781330885523f };

// sig[i] -> x index with symmetric mirror (verified rel_err==0)
__device__ __forceinline__ int map_sig(int i) {
    int m = i - 6;
    m = (m < 0) ? (-1 - m) : m;
    m = (m >= N_IN) ? (2 * N_IN - 1 - m) : m;
    return m;
}

// scalar mirrored path for boundary t's
__device__ __forceinline__ void slow_t(const float* __restrict__ xr, int t,
                                       float& a, float& d) {
    a = 0.f; d = 0.f;
    #pragma unroll
    for (int j = 0; j < 8; j++) {
        const float s = __ldg(xr + map_sig(2 * t + j));
        a = fmaf(LO[j], s, a);
        d = fmaf(HI[j], s, d);
    }
}

// 256-bit global load (sm_100+): 8 consecutive floats, 32B-aligned address
__device__ __forceinline__ void ldg256(const float* __restrict__ p, float r[8]) {
    asm ("ld.global.nc.v8.f32 {%0,%1,%2,%3,%4,%5,%6,%7}, [%8];"
         : "=f"(r[0]), "=f"(r[1]), "=f"(r[2]), "=f"(r[3]),
           "=f"(r[4]), "=f"(r[5]), "=f"(r[6]), "=f"(r[7])
         : "l"(p));
}

// streaming (evict-first) stores
__device__ __forceinline__ void stg128_cs(float* __restrict__ p,
                                          float a, float b, float c, float d) {
    asm volatile ("st.global.cs.v4.f32 [%0], {%1,%2,%3,%4};"
                  :: "l"(p), "f"(a), "f"(b), "f"(c), "f"(d) : "memory");
}
__device__ __forceinline__ void stg32_cs(float* __restrict__ p, float a) {
    asm volatile ("st.global.cs.f32 [%0], %1;" :: "l"(p), "f"(a) : "memory");
}

__global__ __launch_bounds__(THREADS) void dwt_kernel(const float* __restrict__ x,
                                                      float* __restrict__ out)
{
    const int row  = blockIdx.y;
    const int wid  = threadIdx.x >> 5;
    const int lane = threadIdx.x & 31;
    const int wir  = blockIdx.x * WARPS + wid;           // warp index within row, 0..63

    const float* __restrict__ xr = x + (size_t)row * N_IN;
    float* __restrict__ orow = out + (size_t)row * OUTROW;

    const int t = wir * T_PER_WARP + 4 * lane;           // this lane's 4-t start
    const int b = 2 * t - 8;                             // own data base (mult of 8)

    // only warp 0 can underflow (b<0); warp 63 lane-31 extra load ends at x[16383]
    const bool edge = (wir == 0);

    // own 8 floats: ONE contiguous LDG.256 per lane (1KB contiguous per warp)
    float r[8];
    {
        int b0 = b;
        if (edge) b0 = max(b, 0);                        // stays 32B-aligned
        ldg256(xr + b0, r);
    }

    // lane 31: direct load replacing out-of-warp shfl source (x[b+8..b+15])
    float p[8];
    if (lane == 31) {
        int b1 = b + 8;
        if (edge) b1 = max(b1, 0);
        ldg256(xr + b1, p);
    }

    // neighbor lane's 8 floats via shuffle crossbar
    float n[8];
    #pragma unroll
    for (int j = 0; j < 8; j++)
        n[j] = __shfl_down_sync(0xffffffffu, r[j], 1);
    if (lane == 31) {
        #pragma unroll
        for (int j = 0; j < 8; j++) n[j] = p[j];
    }

    // f[j] = sig[2t+j] = x[b+2+j], j = 0..13
    const float f[14] = { r[2], r[3], r[4], r[5], r[6], r[7],
                          n[0], n[1], n[2], n[3], n[4], n[5], n[6], n[7] };

    float ca0=0.f, ca1=0.f, ca2=0.f, ca3=0.f;
    float cd0=0.f, cd1=0.f, cd2=0.f, cd3=0.f;
    #pragma unroll
    for (int j = 0; j < 8; j++) {
        ca0 = fmaf(LO[j], f[j    ], ca0);  cd0 = fmaf(HI[j], f[j    ], cd0);
        ca1 = fmaf(LO[j], f[j + 2], ca1);  cd1 = fmaf(HI[j], f[j + 2], cd1);
        ca2 = fmaf(LO[j], f[j + 4], ca2);  cd2 = fmaf(HI[j], f[j + 4], cd2);
        ca3 = fmaf(LO[j], f[j + 6], ca3);  cd3 = fmaf(HI[j], f[j + 6], cd3);
    }

    // boundary overwrite (mirrored taps or clamped base): t in [0,3] U [8191]
    if (t < 4 || t + 3 > 8190) {
        if (t     < 4 || t     > 8190) slow_t(xr, t,     ca0, cd0);
        if (t + 1 < 4 || t + 1 > 8190) slow_t(xr, t + 1, ca1, cd1);
        if (t + 2 < 4 || t + 2 > 8190) slow_t(xr, t + 2, ca2, cd2);
        if (t + 3 < 4 || t + 3 > 8190) slow_t(xr, t + 3, ca3, cd3);
    }

    // ---- aligned, shuffle-shifted, streaming STG.128 stores ----
    float* __restrict__ gA = orow + t;            // elem index ≡ {0,2} mod 4
    float* __restrict__ gD = orow + T_OUT + t;    // elem index ≡ {3,1} mod 4

    if (((size_t)row & 1) == 0) {
        // cA aligned directly
        stg128_cs(gA, ca0, ca1, ca2, ca3);
        // cD: shift 1 -> {cd1,cd2,cd3,next.cd0} at gD+1
        const float nd0 = __shfl_down_sync(0xffffffffu, cd0, 1);
        if (lane < 31) {
            stg128_cs(gD + 1, cd1, cd2, cd3, nd0);
        } else {
            stg32_cs(gD + 1, cd1); stg32_cs(gD + 2, cd2); stg32_cs(gD + 3, cd3);
        }
        if (lane == 0) stg32_cs(gD, cd0);
    } else {
        // cA: shift 2 -> {ca2,ca3,next.ca0,next.ca1} at gA+2
        const float na0 = __shfl_down_sync(0xffffffffu, ca0, 1);
        const float na1 = __shfl_down_sync(0xffffffffu, ca1, 1);
        if (lane < 31) {
            stg128_cs(gA + 2, ca2, ca3, na0, na1);
        } else {
            stg32_cs(gA + 2, ca2); stg32_cs(gA + 3, ca3);
        }
        if (lane == 0) { stg32_cs(gA, ca0); stg32_cs(gA + 1, ca1); }
        // cD: shift 3 -> {cd3,next.cd0,next.cd1,next.cd2} at gD+3
        const float nd0 = __shfl_down_sync(0xffffffffu, cd0, 1);
        const float nd1 = __shfl_down_sync(0xffffffffu, cd1, 1);
        const float nd2 = __shfl_down_sync(0xffffffffu, cd2, 1);
        if (lane < 31) {
            stg128_cs(gD + 3, cd3, nd0, nd1, nd2);
        } else {
            stg32_cs(gD + 3, cd3);
        }
        if (lane == 0) { stg32_cs(gD, cd0); stg32_cs(gD + 1, cd1); stg32_cs(gD + 2, cd2); }
    }

    // leftover t = 8192..8194 (all mirrored-boundary): 3 lanes of the last warp
    if (wir == WARPS_PER_ROW - 1 && lane < 3) {
        const int tv = 8192 + lane;
        float a, d;
        slow_t(xr, tv, a, d);
        stg32_cs(orow + tv,         a);
        stg32_cs(orow + T_OUT + tv, d);
    }
}

extern "C" void kernel_launch(void* const* d_in, const int* in_sizes, int n_in,
                              void* d_out, int out_size)
{
    const float* x = (const float*)d_in[0];
    float* out = (float*)d_out;
    const int rows = in_sizes[0] / N_IN;   // 4096
    dim3 grid(BLOCKS_PER_ROW, rows);
    dwt_kernel<<<grid, THREADS>>>(x, out);
}

// round 15
// speedup vs baseline: 1.0051x; 1.0016x over previous
#include <cuda_runtime.h>
#include <cstdint>

constexpr int N_IN   = 16384;
constexpr int T_OUT  = 8195;           // ((N+13)-8)/2+1
constexpr int OUTROW = 2 * T_OUT;      // 16390

constexpr int THREADS        = 256;
constexpr int WARPS          = THREADS / 32;   // 8
constexpr int T_PER_LANE     = 8;
constexpr int T_PER_WARP     = 256;            // 8 t per lane
constexpr int WARPS_PER_ROW  = 32;             // t 0..8191; 8192..8194 via tail lanes
constexpr int BLOCKS_PER_ROW = WARPS_PER_ROW / WARPS;   // 4

// time-reversed filters (compile-time immediates -> FFMA-imm)
__device__ constexpr float LO[8] = {  0.23037781330885523f,  0.7148465705525415f,
                                      0.6308807679295904f,  -0.02798376941698385f,
                                     -0.18703481171888114f,  0.030841381835986965f,
                                      0.032883011666982945f,-0.010597401784997278f };
__device__ constexpr float HI[8] = { -0.010597401784997278f,-0.032883011666982945f,
                                      0.030841381835986965f, 0.18703481171888114f,
                                     -0.02798376941698385f, -0.6308807679295904f,
                                      0.7148465705525415f,  -0.23037781330885523f };

// sig[i] -> x index with symmetric mirror (verified rel_err==0)
__device__ __forceinline__ int map_sig(int i) {
    int m = i - 6;
    m = (m < 0) ? (-1 - m) : m;
    m = (m >= N_IN) ? (2 * N_IN - 1 - m) : m;
    return m;
}

// scalar mirrored path for boundary t's
__device__ __forceinline__ void slow_t(const float* __restrict__ xr, int t,
                                       float& a, float& d) {
    a = 0.f; d = 0.f;
    #pragma unroll
    for (int j = 0; j < 8; j++) {
        const float s = __ldg(xr + map_sig(2 * t + j));
        a = fmaf(LO[j], s, a);
        d = fmaf(HI[j], s, d);
    }
}

// 256-bit global load/store (sm_100+), 32B-aligned addresses
__device__ __forceinline__ void ldg256(const float* __restrict__ p, float r[8]) {
    asm ("ld.global.nc.v8.f32 {%0,%1,%2,%3,%4,%5,%6,%7}, [%8];"
         : "=f"(r[0]), "=f"(r[1]), "=f"(r[2]), "=f"(r[3]),
           "=f"(r[4]), "=f"(r[5]), "=f"(r[6]), "=f"(r[7])
         : "l"(p));
}
__device__ __forceinline__ void stg256(float* __restrict__ p, const float v[8]) {
    asm volatile ("st.global.v8.f32 [%0], {%1,%2,%3,%4,%5,%6,%7,%8};"
                  :: "l"(p), "f"(v[0]), "f"(v[1]), "f"(v[2]), "f"(v[3]),
                     "f"(v[4]), "f"(v[5]), "f"(v[6]), "f"(v[7]) : "memory");
}

// shifted 8-wide store: writes v[0..7] to g[0..7] where (elem index of g) % 8 == 8-S.
// Aligned STG.256 at g+S with values {v[S..7], nextlane.v[0..S-1]}; lane0/31 edges scalar.
template<int S>
__device__ __forceinline__ void store8(float* __restrict__ g, const float v[8], int lane) {
    if (S == 0) {
        stg256(g, v);
        return;
    }
    float y[8];
    #pragma unroll
    for (int k = 0; k < 8 - S; k++) y[k] = v[S + k];
    #pragma unroll
    for (int k = 8 - S; k < 8; k++)
        y[k] = __shfl_down_sync(0xffffffffu, v[k - (8 - S)], 1);
    if (lane < 31) {
        stg256(g + S, y);
    } else {
        #pragma unroll
        for (int k = 0; k < 8 - S; k++) g[S + k] = v[S + k];
    }
    if (lane == 0) {
        #pragma unroll
        for (int k = 0; k < S; k++) g[k] = v[k];
    }
}

template<int SA, int SD>
__device__ __forceinline__ void store_tile(float* __restrict__ orow, int t, int lane,
                                           const float ca[8], const float cd[8]) {
    store8<SA>(orow + t,         ca, lane);
    store8<SD>(orow + T_OUT + t, cd, lane);
}

__global__ __launch_bounds__(THREADS) void dwt_kernel(const float* __restrict__ x,
                                                      float* __restrict__ out)
{
    const int row  = blockIdx.y;
    const int wid  = threadIdx.x >> 5;
    const int lane = threadIdx.x & 31;
    const int wir  = blockIdx.x * WARPS + wid;           // warp index within row, 0..31

    const float* __restrict__ xr = x + (size_t)row * N_IN;
    float* __restrict__ orow = out + (size_t)row * OUTROW;

    const int t = wir * T_PER_WARP + T_PER_LANE * lane;  // this lane's 8-t start
    const int b = 2 * t - 8;                             // own base (mult of 16)
    const bool edge = (wir == 0);                        // only lane 0 of warp 0 underflows

    // own 16 floats: two contiguous LDG.256 (2KB contiguous per warp)
    float r[16];
    {
        int b0 = b, b1 = b + 8;
        if (edge) { b0 = max(b0, 0); b1 = max(b1, 0); }  // stay 32B-aligned
        ldg256(xr + b0, r);
        ldg256(xr + b1, r + 8);
    }

    // lane 31: direct load replacing out-of-warp shfl source (x[b+16..b+23]).
    // Max b+16 = 16376 = N-8, min = 504: always in range, no clamp.
    float p[8];
    if (lane == 31) ldg256(xr + b + 16, p);

    // neighbor's first 8 floats via shuffle crossbar
    float n[8];
    #pragma unroll
    for (int j = 0; j < 8; j++)
        n[j] = __shfl_down_sync(0xffffffffu, r[j], 1);
    if (lane == 31) {
        #pragma unroll
        for (int j = 0; j < 8; j++) n[j] = p[j];
    }

    // w[k] = sig[2t+k] = x[b+2+k], k = 0..21
    float w[22];
    #pragma unroll
    for (int k = 0; k < 14; k++) w[k] = r[k + 2];
    #pragma unroll
    for (int k = 0; k < 8; k++)  w[14 + k] = n[k];

    float ca[8], cd[8];
    #pragma unroll
    for (int v = 0; v < 8; v++) {
        float a = 0.f, d = 0.f;
        #pragma unroll
        for (int j = 0; j < 8; j++) {
            a = fmaf(LO[j], w[2 * v + j], a);
            d = fmaf(HI[j], w[2 * v + j], d);
        }
        ca[v] = a; cd[v] = d;
    }

    // boundary overwrite (mirrored taps or clamped base): t in [0,3] U [8191]
    if (t < 4 || t + 7 > 8190) {
        #pragma unroll
        for (int v = 0; v < 8; v++) {
            const int tv = t + v;
            if (tv < 4 || tv > 8190) slow_t(xr, tv, ca[v], cd[v]);
        }
    }

    // ---- fully 256-bit shifted stores; shift pair fixed by row & 3 ----
    // elem(gA) = row*16390 + t  (t mult of 8; 16390 % 8 = 6); elem(gD) = +8195 (%8 = 3)
    switch (row & 3) {
        case 0: store_tile<0, 5>(orow, t, lane, ca, cd); break;
        case 1: store_tile<2, 7>(orow, t, lane, ca, cd); break;
        case 2: store_tile<4, 1>(orow, t, lane, ca, cd); break;
        default: store_tile<6, 3>(orow, t, lane, ca, cd); break;
    }

    // leftover t = 8192..8194 (all mirrored-boundary): 3 lanes of the last warp
    if (wir == WARPS_PER_ROW - 1 && lane < 3) {
        const int tv = 8192 + lane;
        float a, d;
        slow_t(xr, tv, a, d);
        orow[tv]         = a;
        orow[T_OUT + tv] = d;
    }
}

extern "C" void kernel_launch(void* const* d_in, const int* in_sizes, int n_in,
                              void* d_out, int out_size)
{
    const float* x = (const float*)d_in[0];
    float* out = (float*)d_out;
    const int rows = in_sizes[0] / N_IN;   // 4096
    dim3 grid(BLOCKS_PER_ROW, rows);
    dwt_kernel<<<grid, THREADS>>>(x, out);
}